// round 15
// baseline (speedup 1.0000x reference)
#include <cuda_runtime.h>
#include <cuda_fp16.h>
#include <cstdint>

// Problem constants
#define BQ   16
#define TT   1024
#define CC   512
#define MTOT (BQ * TT)      // 16384 rows (b,t)
#define C2   (2 * CC)       // 1024

// ---------------- scratch (device globals; no allocation allowed) -----------
__device__ __half g_xnh[(size_t)MTOT * CC];     // LN output (fp16)
__device__ __half g_h1h[(size_t)MTOT * C2];     // GEMM1+SiLU output (fp16)
__device__ __half g_h2h[(size_t)MTOT * CC];     // conv+GLU+BN output (fp16)
__device__ __half g_w1h[(size_t)C2 * CC];       // fp16 weights
__device__ __half g_w3h[(size_t)CC * CC];
__device__ __half g_w2h[(size_t)5 * C2 * C2];   // w2 permuted+transposed [kc][p][i], fp16
__device__ float  g_b2p[C2];                    // permuted conv bias

// ---------------- helpers ---------------------------------------------------
__device__ __forceinline__ void mma16h(float (&d)[4], const uint32_t (&a)[4], const uint32_t (&b)[2]) {
    asm volatile(
        "mma.sync.aligned.m16n8k16.row.col.f32.f16.f16.f32 "
        "{%0,%1,%2,%3}, {%4,%5,%6,%7}, {%8,%9}, {%0,%1,%2,%3};\n"
        : "+f"(d[0]), "+f"(d[1]), "+f"(d[2]), "+f"(d[3])
        : "r"(a[0]), "r"(a[1]), "r"(a[2]), "r"(a[3]),
          "r"(b[0]), "r"(b[1]));
}
__device__ __forceinline__ void ldsm4(uint32_t& r0, uint32_t& r1, uint32_t& r2, uint32_t& r3,
                                      uint32_t addr) {
    asm volatile("ldmatrix.sync.aligned.m8n8.x4.shared.b16 {%0,%1,%2,%3}, [%4];"
                 : "=r"(r0), "=r"(r1), "=r"(r2), "=r"(r3) : "r"(addr));
}

__device__ __forceinline__ void cpa16(uint32_t dst, const void* src) {
    asm volatile("cp.async.cg.shared.global [%0], [%1], 16;\n" :: "r"(dst), "l"(src));
}
__device__ __forceinline__ void cpa16p(uint32_t dst, const void* src, bool pred) {
    int sz = pred ? 16 : 0;
    asm volatile("cp.async.cg.shared.global [%0], [%1], 16, %2;\n" :: "r"(dst), "l"(src), "r"(sz));
}
__device__ __forceinline__ void cp_commit() { asm volatile("cp.async.commit_group;\n"); }
__device__ __forceinline__ void cp_wait2() { asm volatile("cp.async.wait_group 2;\n"); }

__device__ __forceinline__ float fsigmoid(float v) { return 1.f / (1.f + __expf(-v)); }

// ---------------- 0) weight prep (merged small preps) ------------------------
// i < 131072: w1 -> g_w1h ; i < 196608: w3 -> g_w3h ; i < 197632: b2 perm
__global__ void prep_small(const float* __restrict__ w1, const float* __restrict__ w3,
                           const float* __restrict__ b2) {
    int i = blockIdx.x * blockDim.x + threadIdx.x;
    if (i < 131072) {
        float4 v = ((const float4*)w1)[i];
        ((__half2*)g_w1h)[i * 2]     = __floats2half2_rn(v.x, v.y);
        ((__half2*)g_w1h)[i * 2 + 1] = __floats2half2_rn(v.z, v.w);
    } else if (i < 196608) {
        int j = i - 131072;                    // 65536 float4 = CC*CC/4
        float4 v = ((const float4*)w3)[j];
        ((__half2*)g_w3h)[j * 2]     = __floats2half2_rn(v.x, v.y);
        ((__half2*)g_w3h)[j * 2 + 1] = __floats2half2_rn(v.z, v.w);
    } else if (i < 197632) {
        int p = i - 196608;
        int ch = (p & 1) ? (CC + (p >> 1)) : (p >> 1);
        g_b2p[p] = b2[ch];
    }
}

// w2[kc][i][o] -> g_w2h[kc][p][i] (fp16), p = (o<512) ? 2o : 2(o-512)+1
__global__ void w2_perm_half(const float* __restrict__ w2) {
    __shared__ float tile[32][33];
    int kc = blockIdx.z;
    int i0 = blockIdx.x * 32;
    int o0 = blockIdx.y * 32;
    int tx = threadIdx.x, ty = threadIdx.y;   // 32 x 8
    #pragma unroll
    for (int r = 0; r < 32; r += 8)
        tile[ty + r][tx] = w2[((size_t)kc * C2 + (i0 + ty + r)) * C2 + o0 + tx];
    __syncthreads();
    #pragma unroll
    for (int r = 0; r < 32; r += 8) {
        int o = o0 + ty + r;
        int p = (o < CC) ? (2 * o) : (2 * (o - CC) + 1);
        g_w2h[((size_t)kc * C2 + p) * C2 + i0 + tx] = __float2half_rn(tile[tx][ty + r]);
    }
}

// ---------------- 1) LayerNorm (stores fp16) ---------------------------------
__global__ void ln_kernel(const float* __restrict__ x,
                          const float* __restrict__ lg,
                          const float* __restrict__ lb) {
    int row = blockIdx.x;
    const float2* xin = (const float2*)(x + (size_t)row * CC);
    float2 v = xin[threadIdx.x];
    float s = v.x + v.y;
    float q = v.x * v.x + v.y * v.y;
    #pragma unroll
    for (int o = 16; o; o >>= 1) {
        s += __shfl_xor_sync(0xffffffffu, s, o);
        q += __shfl_xor_sync(0xffffffffu, q, o);
    }
    __shared__ float ss[8], sq[8];
    __shared__ float mu_s, rs_s;
    int w = threadIdx.x >> 5, l = threadIdx.x & 31;
    if (l == 0) { ss[w] = s; sq[w] = q; }
    __syncthreads();
    if (threadIdx.x == 0) {
        float S = 0.f, Q = 0.f;
        #pragma unroll
        for (int i = 0; i < 8; i++) { S += ss[i]; Q += sq[i]; }
        float mu = S * (1.f / CC);
        float var = Q * (1.f / CC) - mu * mu;
        mu_s = mu;
        rs_s = rsqrtf(var + 1e-5f);
    }
    __syncthreads();
    float mu = mu_s, rs = rs_s;
    int c = threadIdx.x * 2;
    float ox = (v.x - mu) * rs * lg[c]     + lb[c];
    float oy = (v.y - mu) * rs * lg[c + 1] + lb[c + 1];
    ((__half2*)(g_xnh + (size_t)row * CC))[threadIdx.x] = __floats2half2_rn(ox, oy);
}

// ---------------- 2/5) fp16 GEMM, ldmatrix, 4-stage/wait2 pipeline -----------
// MODE 0: A = g_xnh -> g_h1h (SiLU, fp16 store). MODE 1: A = g_h2h -> out (fp32).
template <int N, int MODE, int KD>
__global__ __launch_bounds__(256, 2)
void gemm_h(const __half* __restrict__ W, const float* __restrict__ bias,
            float* __restrict__ outParam) {
    extern __shared__ float smf[];
    __half* smh = (__half*)smf;
    constexpr int ROWW = 40;          // halves per row (80 B; bank-bijective, LDSM-safe)
    constexpr int TSZ  = 128 * ROWW;
    __half* AsB = smh;                // 4 stages A
    __half* BsB = smh + 4 * TSZ;      // 4 stages B
    constexpr int KT = KD / 32;

    const __half* A = (MODE == 0) ? g_xnh : g_h2h;

    const int m0 = blockIdx.x * 128, n0 = blockIdx.y * 128;
    const int tid = threadIdx.x;
    const int lane = tid & 31, warp = tid >> 5;
    const int wm = warp & 1, wn = warp >> 1;
    const int g = lane >> 2, t = lane & 3;
    const int sub = lane >> 3, lr = lane & 7;
    const uint32_t aoff = (((sub & 1) * 8 + lr) * ROWW + (sub >> 1) * 8) * 2;
    const uint32_t boff = (((sub >> 1) * 8 + lr) * ROWW + (sub & 1) * 8) * 2;

    auto stage = [&](int s) {
        __half* a = AsB + (s & 3) * TSZ;
        __half* b = BsB + (s & 3) * TSZ;
        const __half* Ab = A + (size_t)m0 * KD + s * 32;
        const __half* Bb = W + (size_t)n0 * KD + s * 32;
        #pragma unroll
        for (int p = 0; p < 2; p++) {
            int c = tid * 2 + p;
            int row = c >> 2, kh = c & 3;
            uint32_t dA = (uint32_t)__cvta_generic_to_shared(a + row * ROWW + kh * 8);
            uint32_t dB = (uint32_t)__cvta_generic_to_shared(b + row * ROWW + kh * 8);
            cpa16(dA, Ab + (size_t)row * KD + kh * 8);
            cpa16(dB, Bb + (size_t)row * KD + kh * 8);
        }
        cp_commit();
    };

    float acc[4][4][4];
    #pragma unroll
    for (int mi = 0; mi < 4; mi++)
        #pragma unroll
        for (int ni = 0; ni < 4; ni++)
            #pragma unroll
            for (int j = 0; j < 4; j++) acc[mi][ni][j] = 0.f;

    auto comp = [&](int s) {
        uint32_t abase = (uint32_t)__cvta_generic_to_shared(AsB + (s & 3) * TSZ) + aoff;
        uint32_t bbase = (uint32_t)__cvta_generic_to_shared(BsB + (s & 3) * TSZ) + boff;
        #pragma unroll
        for (int ks = 0; ks < 2; ks++) {
            uint32_t af[4][4];
            #pragma unroll
            for (int mi = 0; mi < 4; mi++)
                ldsm4(af[mi][0], af[mi][1], af[mi][2], af[mi][3],
                      abase + (wm * 64 + mi * 16) * (ROWW * 2) + ks * 32);
            uint32_t bf[4][2];
            #pragma unroll
            for (int np = 0; np < 2; np++)
                ldsm4(bf[2 * np][0], bf[2 * np][1], bf[2 * np + 1][0], bf[2 * np + 1][1],
                      bbase + (wn * 32 + np * 16) * (ROWW * 2) + ks * 32);
            #pragma unroll
            for (int mi = 0; mi < 4; mi++)
                #pragma unroll
                for (int ni = 0; ni < 4; ni++)
                    mma16h(acc[mi][ni], af[mi], bf[ni]);
        }
    };

    stage(0);
    stage(1);
    stage(2);
    #pragma unroll 1
    for (int kt = 0; kt < KT; ++kt) {
        cp_wait2();                 // <=2 groups pending: B(kt) landed
        __syncthreads();
        if (kt + 3 < KT) stage(kt + 3);
        comp(kt);
    }

    #pragma unroll
    for (int mi = 0; mi < 4; mi++) {
        int r0 = m0 + wm * 64 + mi * 16 + g;
        #pragma unroll
        for (int ni = 0; ni < 4; ni++) {
            int c0 = n0 + wn * 32 + ni * 8 + t * 2;
            float2 v0, v1;
            v0.x = acc[mi][ni][0] + bias[c0];
            v0.y = acc[mi][ni][1] + bias[c0 + 1];
            v1.x = acc[mi][ni][2] + bias[c0];
            v1.y = acc[mi][ni][3] + bias[c0 + 1];
            if (MODE == 0) {
                v0.x = v0.x * fsigmoid(v0.x); v0.y = v0.y * fsigmoid(v0.y);
                v1.x = v1.x * fsigmoid(v1.x); v1.y = v1.y * fsigmoid(v1.y);
                *(__half2*)(g_h1h + (size_t)r0 * N + c0)       = __floats2half2_rn(v0.x, v0.y);
                *(__half2*)(g_h1h + (size_t)(r0 + 8) * N + c0) = __floats2half2_rn(v1.x, v1.y);
            } else {
                *(float2*)(outParam + (size_t)r0 * N + c0)       = v0;
                *(float2*)(outParam + (size_t)(r0 + 8) * N + c0) = v1;
            }
        }
    }
}

// ---------------- 3) Conv1d (K=5), A reused, ldmatrix, 4-buf B/wait2 ---------
__global__ __launch_bounds__(256, 2)
void conv_fp16(const float* __restrict__ bg, const float* __restrict__ bb_,
               const float* __restrict__ bm, const float* __restrict__ bv) {
    extern __shared__ float smf[];
    __half* smh = (__half*)smf;
    constexpr int ROWW = 40;
    constexpr int BTSZ = 128 * ROWW;
    constexpr int AROWS = 136;
    constexpr int ATSZ = AROWS * ROWW;
    __half* AsB = smh;                        // 2 x A tiles
    __half* BsB = smh + 2 * ATSZ;             // 4 x B tiles
    constexpr int NIT = 160;

    const int m0 = blockIdx.x * 128, n0 = blockIdx.y * 128;
    const int bb = m0 >> 10, t0 = m0 & 1023;
    const int tid = threadIdx.x;
    const int lane = tid & 31, warp = tid >> 5;
    const int wm = warp & 1, wn = warp >> 1;
    const int g = lane >> 2, t = lane & 3;
    const int sub = lane >> 3, lr = lane & 7;
    const uint32_t aoff = (((sub & 1) * 8 + lr) * ROWW + (sub >> 1) * 8) * 2;
    const uint32_t boff = (((sub >> 1) * 8 + lr) * ROWW + (sub & 1) * 8) * 2;

    auto stageA = [&](int kt) {
        __half* a = AsB + (kt & 1) * ATSZ;
        const __half* Ab = g_h1h + (size_t)(bb * TT) * C2 + kt * 32;
        #pragma unroll
        for (int p = 0; p < 2; p++) {
            int c = tid + p * 256;
            int row = c >> 2, kh = c & 3;
            uint32_t d = (uint32_t)__cvta_generic_to_shared(a + row * ROWW + kh * 8);
            int trow = t0 + row - 2;
            bool ok = (trow >= 0) && (trow < TT);
            cpa16p(d, Ab + (size_t)(ok ? trow : 0) * C2 + kh * 8, ok);
        }
        if (tid < 32) {
            int c = tid + 512;
            int row = c >> 2, kh = c & 3;
            uint32_t d = (uint32_t)__cvta_generic_to_shared(a + row * ROWW + kh * 8);
            int trow = t0 + row - 2;
            bool ok = (trow >= 0) && (trow < TT);
            cpa16p(d, Ab + (size_t)(ok ? trow : 0) * C2 + kh * 8, ok);
        }
    };

    auto stageB = [&](int s) {
        int kt = s / 5;
        int kc = s - kt * 5;
        __half* b = BsB + (s & 3) * BTSZ;
        const __half* Bb = g_w2h + ((size_t)kc * C2 + n0) * C2 + kt * 32;
        #pragma unroll
        for (int p = 0; p < 2; p++) {
            int c = tid * 2 + p;
            int row = c >> 2, kh = c & 3;
            uint32_t d = (uint32_t)__cvta_generic_to_shared(b + row * ROWW + kh * 8);
            cpa16(d, Bb + (size_t)row * C2 + kh * 8);
        }
    };

    float acc[4][4][4];
    #pragma unroll
    for (int mi = 0; mi < 4; mi++)
        #pragma unroll
        for (int ni = 0; ni < 4; ni++)
            #pragma unroll
            for (int j = 0; j < 4; j++) acc[mi][ni][j] = 0.f;

    auto comp = [&](int s) {
        int kt = s / 5;
        int kc = s - kt * 5;
        uint32_t abase = (uint32_t)__cvta_generic_to_shared(AsB + (kt & 1) * ATSZ)
                       + kc * (ROWW * 2) + aoff;
        uint32_t bbase = (uint32_t)__cvta_generic_to_shared(BsB + (s & 3) * BTSZ) + boff;
        #pragma unroll
        for (int ks = 0; ks < 2; ks++) {
            uint32_t af[4][4];
            #pragma unroll
            for (int mi = 0; mi < 4; mi++)
                ldsm4(af[mi][0], af[mi][1], af[mi][2], af[mi][3],
                      abase + (wm * 64 + mi * 16) * (ROWW * 2) + ks * 32);
            uint32_t bf[4][2];
            #pragma unroll
            for (int np = 0; np < 2; np++)
                ldsm4(bf[2 * np][0], bf[2 * np][1], bf[2 * np + 1][0], bf[2 * np + 1][1],
                      bbase + (wn * 32 + np * 16) * (ROWW * 2) + ks * 32);
            #pragma unroll
            for (int mi = 0; mi < 4; mi++)
                #pragma unroll
                for (int ni = 0; ni < 4; ni++)
                    mma16h(acc[mi][ni], af[mi], bf[ni]);
        }
    };

    // Prologue: g0={A(0),B(0)}, g1={B(1)}, g2={B(2)}
    stageA(0); stageB(0); cp_commit();
    stageB(1); cp_commit();
    stageB(2); cp_commit();

    #pragma unroll 1
    for (int s = 0; s < NIT; ++s) {
        cp_wait2();                 // retires through g_{s+1}: B(s+1), A(s/5) landed
        __syncthreads();
        if (s % 5 == 0) {
            int ktn = s / 5 + 1;
            if (ktn < 32) stageA(ktn);
        }
        if (s + 3 < NIT) stageB(s + 3);
        cp_commit();
        comp(s);
    }

    // Fused epilogue: bias -> GLU -> BN -> fp16 -> g_h2h
    #pragma unroll
    for (int mi = 0; mi < 4; mi++) {
        int r0 = m0 + wm * 64 + mi * 16 + g;
        #pragma unroll
        for (int ni = 0; ni < 4; ni++) {
            int c0 = n0 + wn * 32 + ni * 8 + t * 2;
            int j  = c0 >> 1;
            float ba = g_b2p[c0], bgg = g_b2p[c0 + 1];
            float sc = bg[j] * rsqrtf(bv[j] + 1e-5f);
            float mean = bm[j], beta = bb_[j];
            float a0 = acc[mi][ni][0] + ba, g0 = acc[mi][ni][1] + bgg;
            float a1 = acc[mi][ni][2] + ba, g1 = acc[mi][ni][3] + bgg;
            float o0 = a0 * fsigmoid(g0);
            float o1 = a1 * fsigmoid(g1);
            g_h2h[(size_t)r0 * CC + j]       = __float2half_rn((o0 - mean) * sc + beta);
            g_h2h[(size_t)(r0 + 8) * CC + j] = __float2half_rn((o1 - mean) * sc + beta);
        }
    }
}

// ---------------- launch -----------------------------------------------------
extern "C" void kernel_launch(void* const* d_in, const int* in_sizes, int n_in,
                              void* d_out, int out_size) {
    const float* x     = (const float*)d_in[0];
    const float* ln_g  = (const float*)d_in[1];
    const float* ln_b  = (const float*)d_in[2];
    const float* w1    = (const float*)d_in[3];
    const float* b1    = (const float*)d_in[4];
    const float* w2    = (const float*)d_in[5];
    const float* b2    = (const float*)d_in[6];
    const float* bn_g  = (const float*)d_in[7];
    const float* bn_b  = (const float*)d_in[8];
    const float* bn_m  = (const float*)d_in[9];
    const float* bn_v  = (const float*)d_in[10];
    const float* w3    = (const float*)d_in[11];
    const float* b3    = (const float*)d_in[12];
    float* out = (float*)d_out;

    const int smem_gemm = 8 * 128 * 40 * 2;                        // 81920
    const int smem_conv = (2 * 136 * 40 + 4 * 128 * 40) * 2;       // 62720
    cudaFuncSetAttribute(gemm_h<C2, 0, CC>,
                         cudaFuncAttributeMaxDynamicSharedMemorySize, smem_gemm);
    cudaFuncSetAttribute(gemm_h<CC, 1, CC>,
                         cudaFuncAttributeMaxDynamicSharedMemorySize, smem_gemm);
    cudaFuncSetAttribute(conv_fp16,
                         cudaFuncAttributeMaxDynamicSharedMemorySize, smem_conv);

    // Device addresses of __device__ weight buffers (host shadow is NOT valid!)
    __half *w1h, *w3h;
    cudaGetSymbolAddress((void**)&w1h, g_w1h);
    cudaGetSymbolAddress((void**)&w3h, g_w3h);

    prep_small<<<(197632 + 255) / 256, 256>>>(w1, w3, b2);
    w2_perm_half<<<dim3(C2 / 32, C2 / 32, 5), dim3(32, 8)>>>(w2);

    ln_kernel<<<MTOT, 256>>>(x, ln_g, ln_b);
    gemm_h<C2, 0, CC><<<dim3(MTOT / 128, C2 / 128), 256, smem_gemm>>>(w1h, b1, nullptr);
    conv_fp16<<<dim3(MTOT / 128, C2 / 128), 256, smem_conv>>>(bn_g, bn_b, bn_m, bn_v);
    gemm_h<CC, 1, CC><<<dim3(MTOT / 128, CC / 128), 256, smem_gemm>>>(w3h, b3, out);
}